// round 4
// baseline (speedup 1.0000x reference)
#include <cuda_runtime.h>
#include <math.h>

// ---------------- problem constants ----------------
#define HDIM   1024
#define NH     16
#define HD     64
#define INTER  2048
#define NE     8
#define SEQ    1024
#define NBATCH 4
#define NTOK   4096          // NBATCH*SEQ
#define TQKV   3072          // (NH + 2*NKV)*HD
#define SLOTS  8192          // NTOK * TOPK

// ---------------- scratch (static device globals; no allocation) ----------------
__device__ float g_hn[(size_t)NTOK * HDIM];              // rmsnorm1 out
__device__ float g_qkv[(size_t)NTOK * TQKV];             // qkv proj
__device__ float g_attn[(size_t)NTOK * HDIM];            // attention out (pre o-proj)
__device__ float g_hf[(size_t)NTOK * HDIM];              // rmsnorm2 out
__device__ float g_xg[(size_t)(SLOTS + 128) * HDIM];     // gathered tokens (padded rows)
__device__ float g_gu[(size_t)SLOTS * 2 * INTER];        // gate_up output
__device__ float g_act[(size_t)(SLOTS + 128) * INTER];   // silu(g)*u (padded rows)
__device__ float g_dn[(size_t)SLOTS * HDIM];             // down proj per-slot
__device__ int   g_cnt[NE];
__device__ int   g_off[NE];
__device__ int   g_cur[NE];
__device__ int   g_tok_e[NTOK * 2];
__device__ int   g_tok_slot[NTOK * 2];
__device__ float g_tok_w[NTOK * 2];

// ---------------- small kernels ----------------
__global__ void zero_kernel() {
    if (threadIdx.x < NE) g_cnt[threadIdx.x] = 0;
}

// one block per token, 256 threads, 1 float4 each
__global__ void rmsnorm_kernel(const float* __restrict__ x,
                               const float* __restrict__ w,
                               float* __restrict__ y) {
    int t = blockIdx.x, tid = threadIdx.x;
    const float4 v = ((const float4*)(x + (size_t)t * HDIM))[tid];
    float ss = v.x * v.x + v.y * v.y + v.z * v.z + v.w * v.w;
    __shared__ float red[8];
    #pragma unroll
    for (int o = 16; o; o >>= 1) ss += __shfl_xor_sync(0xffffffffu, ss, o);
    if ((tid & 31) == 0) red[tid >> 5] = ss;
    __syncthreads();
    if (tid < 8) {
        float s2 = red[tid];
        #pragma unroll
        for (int o = 4; o; o >>= 1) s2 += __shfl_xor_sync(0xffu, s2, o);
        if (tid == 0) red[0] = s2;
    }
    __syncthreads();
    float inv = rsqrtf(red[0] * (1.0f / HDIM) + 1e-6f);
    const float4 wv = ((const float4*)w)[tid];
    float4 r = make_float4(v.x * inv * wv.x, v.y * inv * wv.y,
                           v.z * inv * wv.z, v.w * inv * wv.w);
    ((float4*)(y + (size_t)t * HDIM))[tid] = r;
}

// ---------------- SGEMM 128x128x8, 8x8 per thread, 256 threads ----------------
#define BM 128
#define BN 128
#define BKC 8

__device__ __forceinline__ void sgemm_body(
    const float* __restrict__ A, const float* __restrict__ B, float* __restrict__ C,
    int N, int K, int Meff, const float* __restrict__ res)
{
    __shared__ float As[BKC][BM];
    __shared__ float Bs[BKC][BN];
    const int tid = threadIdx.x;
    const int bx = blockIdx.x, by = blockIdx.y;
    const int aRow = tid >> 1;
    const int aCol = (tid & 1) << 2;
    const int bRow = tid >> 5;
    const int bCol = (tid & 31) << 2;
    const int tx = tid & 15, ty = tid >> 4;

    const float* Ap = A + (size_t)(by * BM + aRow) * K + aCol;
    const float* Bp = B + (size_t)bRow * N + bx * BN + bCol;

    float acc[8][8];
    #pragma unroll
    for (int i = 0; i < 8; i++)
        #pragma unroll
        for (int j = 0; j < 8; j++) acc[i][j] = 0.0f;

    for (int k0 = 0; k0 < K; k0 += BKC) {
        float4 a4 = *(const float4*)Ap;
        float4 b4 = *(const float4*)Bp;
        As[aCol + 0][aRow] = a4.x;
        As[aCol + 1][aRow] = a4.y;
        As[aCol + 2][aRow] = a4.z;
        As[aCol + 3][aRow] = a4.w;
        *(float4*)(&Bs[bRow][bCol]) = b4;
        __syncthreads();
        #pragma unroll
        for (int kk = 0; kk < BKC; kk++) {
            float ar[8], br[8];
            *(float4*)(ar)     = *(const float4*)(&As[kk][ty * 4]);
            *(float4*)(ar + 4) = *(const float4*)(&As[kk][ty * 4 + 64]);
            *(float4*)(br)     = *(const float4*)(&Bs[kk][tx * 4]);
            *(float4*)(br + 4) = *(const float4*)(&Bs[kk][tx * 4 + 64]);
            #pragma unroll
            for (int i = 0; i < 8; i++)
                #pragma unroll
                for (int j = 0; j < 8; j++)
                    acc[i][j] = fmaf(ar[i], br[j], acc[i][j]);
        }
        __syncthreads();
        Ap += BKC;
        Bp += (size_t)BKC * N;
    }

    #pragma unroll
    for (int i = 0; i < 8; i++) {
        int r = by * BM + ty * 4 + ((i < 4) ? i : (64 + i - 4));
        if (r >= Meff) continue;
        #pragma unroll
        for (int jh = 0; jh < 2; jh++) {
            int c = bx * BN + tx * 4 + jh * 64;
            float4 v = make_float4(acc[i][jh * 4 + 0], acc[i][jh * 4 + 1],
                                   acc[i][jh * 4 + 2], acc[i][jh * 4 + 3]);
            if (res) {
                const float4 rv = *(const float4*)(res + (size_t)r * N + c);
                v.x += rv.x; v.y += rv.y; v.z += rv.z; v.w += rv.w;
            }
            *(float4*)(C + (size_t)r * N + c) = v;
        }
    }
}

__global__ void sgemm_plain(const float* __restrict__ A, const float* __restrict__ B,
                            float* __restrict__ C, int N, int K,
                            const float* __restrict__ res) {
    sgemm_body(A, B, C, N, K, 1 << 30, res);
}

// batched expert GEMM: blockIdx.z = expert; rows start at g_off[e], count g_cnt[e]
__global__ void sgemm_moe(const float* __restrict__ A0, const float* __restrict__ B0,
                          float* __restrict__ C0, int N, int K, long long strideB) {
    int e = blockIdx.z;
    int Meff = g_cnt[e];
    if ((int)blockIdx.y * BM >= Meff) return;
    int off = g_off[e];
    const float* A = A0 + (size_t)off * K;
    const float* B = B0 + (size_t)e * strideB;
    float* C = C0 + (size_t)off * N;
    sgemm_body(A, B, C, N, K, Meff, nullptr);
}

// ---------------- flash attention (fp32) ----------------
// grid: (SEQ/64, NBATCH*NH). block: 256 (16x16). 64q x 64k tiles, HD=64.
#define ATTN_SMEM ((64*64 + 64*65 + 64*68 + 64*68) * 4)

__global__ void attn_kernel(const float* __restrict__ qkv,
                            const float* __restrict__ mask,
                            float* __restrict__ out) {
    extern __shared__ float sm[];
    float* Qs = sm;                 // [64][64]
    float* Kt = Qs + 64 * 64;       // [64 d][65]  (d-major)
    float* Vs = Kt + 64 * 65;       // [64 kv][68]
    float* Ps = Vs + 64 * 68;       // [64 q][68]

    const int tid = threadIdx.x;
    const int qb = blockIdx.x;
    const int bh = blockIdx.y;
    const int b = bh >> 4, h = bh & 15;
    const int s0 = qb * 64;
    const int tx = tid & 15, ty = tid >> 4;

    // load + pre-scale Q (1/sqrt(64) = 0.125)
    for (int idx = tid; idx < 64 * 16; idx += 256) {
        int r = idx >> 4, c4 = (idx & 15) << 2;
        float4 v = *(const float4*)(qkv + (size_t)(b * SEQ + s0 + r) * TQKV + h * HD + c4);
        v.x *= 0.125f; v.y *= 0.125f; v.z *= 0.125f; v.w *= 0.125f;
        *(float4*)(Qs + r * 64 + c4) = v;
    }

    float m[4], l[4], o[4][4];
    #pragma unroll
    for (int i = 0; i < 4; i++) {
        m[i] = -3.0e38f; l[i] = 0.0f;
        #pragma unroll
        for (int j = 0; j < 4; j++) o[i][j] = 0.0f;
    }

    for (int kt = 0; kt < SEQ / 64; kt++) {
        __syncthreads();   // previous tile's Ps/Vs reads done; Q load done (iter 0)
        const int k0 = kt * 64;
        for (int idx = tid; idx < 64 * 16; idx += 256) {
            int r = idx >> 4, c4 = (idx & 15) << 2;
            const float* src = qkv + (size_t)(b * SEQ + k0 + r) * TQKV + NH * HD + h * HD + c4;
            float4 kv = *(const float4*)src;
            Kt[(c4 + 0) * 65 + r] = kv.x;
            Kt[(c4 + 1) * 65 + r] = kv.y;
            Kt[(c4 + 2) * 65 + r] = kv.z;
            Kt[(c4 + 3) * 65 + r] = kv.w;
            float4 vv = *(const float4*)(src + NH * HD);   // v block is +1024 after k start
            *(float4*)(Vs + r * 68 + c4) = vv;
        }
        __syncthreads();

        // scores: rows ty*4+i, cols tx*4+j, init with mask
        float sv[4][4];
        #pragma unroll
        for (int i = 0; i < 4; i++) {
            float4 mk = *(const float4*)(mask + (size_t)(s0 + ty * 4 + i) * SEQ + k0 + tx * 4);
            sv[i][0] = mk.x; sv[i][1] = mk.y; sv[i][2] = mk.z; sv[i][3] = mk.w;
        }
        #pragma unroll 8
        for (int kk = 0; kk < 64; kk++) {
            float qf[4], kf[4];
            #pragma unroll
            for (int i = 0; i < 4; i++) qf[i] = Qs[(ty * 4 + i) * 64 + kk];
            #pragma unroll
            for (int j = 0; j < 4; j++) kf[j] = Kt[kk * 65 + tx * 4 + j];
            #pragma unroll
            for (int i = 0; i < 4; i++)
                #pragma unroll
                for (int j = 0; j < 4; j++)
                    sv[i][j] = fmaf(qf[i], kf[j], sv[i][j]);
        }

        // online softmax per row (reduce over 16-lane tx groups)
        #pragma unroll
        for (int i = 0; i < 4; i++) {
            float tm = fmaxf(fmaxf(sv[i][0], sv[i][1]), fmaxf(sv[i][2], sv[i][3]));
            #pragma unroll
            for (int off = 1; off < 16; off <<= 1)
                tm = fmaxf(tm, __shfl_xor_sync(0xffffffffu, tm, off));
            float mn = fmaxf(m[i], tm);
            float corr = __expf(m[i] - mn);
            float rs = 0.0f;
            #pragma unroll
            for (int j = 0; j < 4; j++) {
                float p = __expf(sv[i][j] - mn);
                sv[i][j] = p;
                rs += p;
            }
            #pragma unroll
            for (int off = 1; off < 16; off <<= 1)
                rs += __shfl_xor_sync(0xffffffffu, rs, off);
            l[i] = l[i] * corr + rs;
            m[i] = mn;
            #pragma unroll
            for (int j = 0; j < 4; j++) o[i][j] *= corr;
            *(float4*)(Ps + (ty * 4 + i) * 68 + tx * 4) =
                make_float4(sv[i][0], sv[i][1], sv[i][2], sv[i][3]);
        }
        __syncthreads();

        // O += P @ V   (output dims = tx*4 + j)
        #pragma unroll 8
        for (int kk = 0; kk < 64; kk++) {
            float pf[4];
            #pragma unroll
            for (int i = 0; i < 4; i++) pf[i] = Ps[(ty * 4 + i) * 68 + kk];
            float4 vv = *(const float4*)(Vs + kk * 68 + tx * 4);
            #pragma unroll
            for (int i = 0; i < 4; i++) {
                o[i][0] = fmaf(pf[i], vv.x, o[i][0]);
                o[i][1] = fmaf(pf[i], vv.y, o[i][1]);
                o[i][2] = fmaf(pf[i], vv.z, o[i][2]);
                o[i][3] = fmaf(pf[i], vv.w, o[i][3]);
            }
        }
    }

    #pragma unroll
    for (int i = 0; i < 4; i++) {
        float inv = 1.0f / l[i];
        float4 r = make_float4(o[i][0] * inv, o[i][1] * inv, o[i][2] * inv, o[i][3] * inv);
        *(float4*)(out + (size_t)(b * SEQ + s0 + ty * 4 + i) * HDIM + h * HD + tx * 4) = r;
    }
}

// ---------------- router / routing machinery ----------------
__global__ void router_kernel(const float* __restrict__ hf, const float* __restrict__ rw) {
    int t = blockIdx.x, tid = threadIdx.x;
    int w = tid >> 5, lane = tid & 31;
    __shared__ float logits[NE];
    float s = 0.0f;
    for (int i = lane; i < HDIM; i += 32)
        s += hf[(size_t)t * HDIM + i] * __ldg(rw + (size_t)i * NE + w);
    #pragma unroll
    for (int o = 16; o; o >>= 1) s += __shfl_xor_sync(0xffffffffu, s, o);
    if (lane == 0) logits[w] = s;
    __syncthreads();
    if (tid == 0) {
        int e0 = 0; float b0 = logits[0];
        #pragma unroll
        for (int e = 1; e < NE; e++) if (logits[e] > b0) { b0 = logits[e]; e0 = e; }
        int e1 = -1; float b1 = -3.0e38f;
        #pragma unroll
        for (int e = 0; e < NE; e++)
            if (e != e0 && logits[e] > b1) { b1 = logits[e]; e1 = e; }
        float w0 = 1.0f / (1.0f + expf(b1 - b0));
        g_tok_e[t * 2 + 0] = e0;
        g_tok_e[t * 2 + 1] = e1;
        g_tok_w[t * 2 + 0] = w0;
        g_tok_w[t * 2 + 1] = 1.0f - w0;
        atomicAdd(&g_cnt[e0], 1);
        atomicAdd(&g_cnt[e1], 1);
    }
}

__global__ void scan_kernel() {
    if (threadIdx.x == 0) {
        int acc = 0;
        for (int e = 0; e < NE; e++) {
            g_off[e] = acc;
            acc += g_cnt[e];
            g_cur[e] = 0;
        }
    }
}

__global__ void assign_gather_kernel(const float* __restrict__ hf) {
    int t = blockIdx.x, tid = threadIdx.x;
    __shared__ int sl[2];
    if (tid < 2) {
        int e = g_tok_e[t * 2 + tid];
        int s = g_off[e] + atomicAdd(&g_cur[e], 1);
        sl[tid] = s;
        g_tok_slot[t * 2 + tid] = s;
    }
    __syncthreads();
    float4 v = ((const float4*)(hf + (size_t)t * HDIM))[tid];
    ((float4*)(g_xg + (size_t)sl[0] * HDIM))[tid] = v;
    ((float4*)(g_xg + (size_t)sl[1] * HDIM))[tid] = v;
}

// silu(g)*u over all SLOTS rows (all rows valid: counts sum to SLOTS exactly)
__global__ void silu_kernel() {
    size_t idx = (size_t)blockIdx.x * 256 + threadIdx.x;  // float4 index
    int row = (int)(idx >> 9);          // INTER/4 = 512 float4 per row
    int jj = (int)(idx & 511) << 2;
    const float* g = g_gu + (size_t)row * (2 * INTER) + jj;
    float4 gv = *(const float4*)g;
    float4 uv = *(const float4*)(g + INTER);
    float4 r;
    r.x = gv.x / (1.0f + expf(-gv.x)) * uv.x;
    r.y = gv.y / (1.0f + expf(-gv.y)) * uv.y;
    r.z = gv.z / (1.0f + expf(-gv.z)) * uv.z;
    r.w = gv.w / (1.0f + expf(-gv.w)) * uv.w;
    *(float4*)(g_act + (size_t)row * INTER + jj) = r;
}

// out[t] += w0*dn[slot0] + w1*dn[slot1]   (deterministic, no atomics)
__global__ void combine_kernel(float* __restrict__ out) {
    int t = blockIdx.x, tid = threadIdx.x;
    int s0 = g_tok_slot[t * 2 + 0], s1 = g_tok_slot[t * 2 + 1];
    float w0 = g_tok_w[t * 2 + 0], w1 = g_tok_w[t * 2 + 1];
    float4 x = ((float4*)(out + (size_t)t * HDIM))[tid];
    float4 a = ((const float4*)(g_dn + (size_t)s0 * HDIM))[tid];
    float4 b = ((const float4*)(g_dn + (size_t)s1 * HDIM))[tid];
    x.x += w0 * a.x + w1 * b.x;
    x.y += w0 * a.y + w1 * b.y;
    x.z += w0 * a.z + w1 * b.z;
    x.w += w0 * a.w + w1 * b.w;
    ((float4*)(out + (size_t)t * HDIM))[tid] = x;
}

// ---------------- launch ----------------
extern "C" void kernel_launch(void* const* d_in, const int* in_sizes, int n_in,
                              void* d_out, int out_size) {
    const float* hidden = (const float*)d_in[0];
    const float* mask   = (const float*)d_in[1];
    const float* ln1    = (const float*)d_in[2];
    const float* ln2    = (const float*)d_in[3];
    const float* qkv_w  = (const float*)d_in[4];
    const float* o_w    = (const float*)d_in[5];
    const float* rt_w   = (const float*)d_in[6];
    const float* gup    = (const float*)d_in[7];
    const float* dwn    = (const float*)d_in[8];
    float* out = (float*)d_out;

    float *hn, *qkvb, *attnb, *hfb, *xg, *gu, *act, *dn;
    cudaGetSymbolAddress((void**)&hn,    g_hn);
    cudaGetSymbolAddress((void**)&qkvb,  g_qkv);
    cudaGetSymbolAddress((void**)&attnb, g_attn);
    cudaGetSymbolAddress((void**)&hfb,   g_hf);
    cudaGetSymbolAddress((void**)&xg,    g_xg);
    cudaGetSymbolAddress((void**)&gu,    g_gu);
    cudaGetSymbolAddress((void**)&act,   g_act);
    cudaGetSymbolAddress((void**)&dn,    g_dn);

    cudaFuncSetAttribute(attn_kernel, cudaFuncAttributeMaxDynamicSharedMemorySize, ATTN_SMEM);

    zero_kernel<<<1, 32>>>();

    // attention block
    rmsnorm_kernel<<<NTOK, 256>>>(hidden, ln1, hn);
    sgemm_plain<<<dim3(TQKV / BN, NTOK / BM), 256>>>(hn, qkv_w, qkvb, TQKV, HDIM, nullptr);
    attn_kernel<<<dim3(SEQ / 64, NBATCH * NH), 256, ATTN_SMEM>>>(qkvb, mask, attnb);
    // o-proj + residual -> out holds x1
    sgemm_plain<<<dim3(HDIM / BN, NTOK / BM), 256>>>(attnb, o_w, out, HDIM, HDIM, hidden);

    // moe block (routed top-2)
    rmsnorm_kernel<<<NTOK, 256>>>(out, ln2, hfb);
    router_kernel<<<NTOK, 256>>>(hfb, rt_w);
    scan_kernel<<<1, 32>>>();
    assign_gather_kernel<<<NTOK, 256>>>(hfb);

    sgemm_moe<<<dim3(2 * INTER / BN, NTOK / BM, NE), 256>>>(
        xg, gup, gu, 2 * INTER, HDIM, (long long)HDIM * 2 * INTER);
    silu_kernel<<<(SLOTS * (INTER / 4)) / 256, 256>>>();
    sgemm_moe<<<dim3(HDIM / BN, NTOK / BM, NE), 256>>>(
        act, dwn, dn, HDIM, INTER, (long long)INTER * HDIM);

    combine_kernel<<<NTOK, 256>>>(out);
}

// round 6
// speedup vs baseline: 3.5652x; 3.5652x over previous
#include <cuda_runtime.h>
#include <cuda_bf16.h>
#include <math.h>
#include <stdint.h>

// ---------------- problem constants ----------------
#define HDIM   1024
#define NH     16
#define HD     64
#define INTER  2048
#define NE     8
#define SEQ    1024
#define NBATCH 4
#define NTOK   4096
#define TQKV   3072
#define SLOTS  8192

// ---------------- scratch ----------------
__device__ float g_qkv[(size_t)NTOK * TQKV];
__device__ float g_hf[(size_t)NTOK * HDIM];
__device__ float g_gu[(size_t)SLOTS * 2 * INTER];
__device__ float g_dn[(size_t)SLOTS * HDIM];

__device__ __nv_bfloat16 g_hnbf[(size_t)NTOK * 2 * HDIM];
__device__ __nv_bfloat16 g_attnbf[(size_t)NTOK * 2 * HDIM];
__device__ __nv_bfloat16 g_xgbf[(size_t)(SLOTS + 128) * 2 * HDIM];
__device__ __nv_bfloat16 g_actbf[(size_t)(SLOTS + 128) * 2 * INTER];

__device__ __nv_bfloat16 g_qkvwt[(size_t)TQKV * 2 * HDIM];
__device__ __nv_bfloat16 g_owt[(size_t)HDIM * 2 * HDIM];
__device__ __nv_bfloat16 g_gupt[(size_t)NE * 2 * INTER * 2 * HDIM];
__device__ __nv_bfloat16 g_dwnt[(size_t)NE * HDIM * 2 * INTER];

__device__ int   g_cnt[NE];
__device__ int   g_off[NE];
__device__ int   g_cur[NE];
__device__ int   g_tok_e[NTOK * 2];
__device__ int   g_tok_slot[NTOK * 2];
__device__ float g_tok_w[NTOK * 2];

// ---------------- PTX helpers ----------------
__device__ __forceinline__ uint32_t smem_u32(const void* p) {
    uint32_t a;
    asm("{ .reg .u64 t; cvta.to.shared.u64 t, %1; cvt.u32.u64 %0, t; }" : "=r"(a) : "l"(p));
    return a;
}
#define CP16(dst, src) asm volatile("cp.async.cg.shared.global [%0], [%1], 16;\n" :: "r"(dst), "l"(src) : "memory")
#define CPCOMMIT()     asm volatile("cp.async.commit_group;\n" ::: "memory")
#define CPWAIT(n)      asm volatile("cp.async.wait_group %0;\n" :: "n"(n) : "memory")

__device__ __forceinline__ void ldmA(uint32_t* a, uint32_t addr) {
    asm volatile("ldmatrix.sync.aligned.m8n8.x4.shared.b16 {%0,%1,%2,%3},[%4];"
        : "=r"(a[0]), "=r"(a[1]), "=r"(a[2]), "=r"(a[3]) : "r"(addr));
}
__device__ __forceinline__ void ldmB(uint32_t* b, uint32_t addr) {
    asm volatile("ldmatrix.sync.aligned.m8n8.x2.shared.b16 {%0,%1},[%2];"
        : "=r"(b[0]), "=r"(b[1]) : "r"(addr));
}
__device__ __forceinline__ void mma_bf16(float* d, const uint32_t* a, const uint32_t* b) {
    asm volatile("mma.sync.aligned.m16n8k16.row.col.f32.bf16.bf16.f32 "
                 "{%0,%1,%2,%3},{%4,%5,%6,%7},{%8,%9},{%0,%1,%2,%3};"
        : "+f"(d[0]), "+f"(d[1]), "+f"(d[2]), "+f"(d[3])
        : "r"(a[0]), "r"(a[1]), "r"(a[2]), "r"(a[3]), "r"(b[0]), "r"(b[1]));
}

__device__ __forceinline__ uint32_t swz(uint32_t o) { return o ^ ((o >> 3) & 0x70); }

// ---------------- hi/lo split helpers ----------------
__device__ __forceinline__ void store_hilo4(__nv_bfloat16* hip, __nv_bfloat16* lop, float4 v) {
    __nv_bfloat162 h0, h1, l0, l1;
    h0.x = __float2bfloat16(v.x); h0.y = __float2bfloat16(v.y);
    h1.x = __float2bfloat16(v.z); h1.y = __float2bfloat16(v.w);
    l0.x = __float2bfloat16(v.x - __bfloat162float(h0.x));
    l0.y = __float2bfloat16(v.y - __bfloat162float(h0.y));
    l1.x = __float2bfloat16(v.z - __bfloat162float(h1.x));
    l1.y = __float2bfloat16(v.w - __bfloat162float(h1.y));
    *(__nv_bfloat162*)hip = h0; *(__nv_bfloat162*)(hip + 2) = h1;
    *(__nv_bfloat162*)lop = l0; *(__nv_bfloat162*)(lop + 2) = l1;
}

// ---------------- small kernels ----------------
__global__ void zero_kernel() { if (threadIdx.x < NE) g_cnt[threadIdx.x] = 0; }

__global__ void rmsnorm_kernel(const float* __restrict__ x, const float* __restrict__ w,
                               float* __restrict__ yf, __nv_bfloat16* __restrict__ yb) {
    int t = blockIdx.x, tid = threadIdx.x;
    const float4 v = ((const float4*)(x + (size_t)t * HDIM))[tid];
    float ss = v.x * v.x + v.y * v.y + v.z * v.z + v.w * v.w;
    __shared__ float red[8];
    #pragma unroll
    for (int o = 16; o; o >>= 1) ss += __shfl_xor_sync(0xffffffffu, ss, o);
    if ((tid & 31) == 0) red[tid >> 5] = ss;
    __syncthreads();
    if (tid < 8) {
        float s2 = red[tid];
        #pragma unroll
        for (int o = 4; o; o >>= 1) s2 += __shfl_xor_sync(0xffu, s2, o);
        if (tid == 0) red[0] = s2;
    }
    __syncthreads();
    float inv = rsqrtf(red[0] * (1.0f / HDIM) + 1e-6f);
    const float4 wv = ((const float4*)w)[tid];
    float4 r = make_float4(v.x * inv * wv.x, v.y * inv * wv.y,
                           v.z * inv * wv.z, v.w * inv * wv.w);
    if (yf) ((float4*)(yf + (size_t)t * HDIM))[tid] = r;
    if (yb) store_hilo4(yb + (size_t)t * 2 * HDIM + tid * 4,
                        yb + (size_t)t * 2 * HDIM + HDIM + tid * 4, r);
}

// W[b][K][N] fp32 -> Wt[b][N][2K] bf16 (hi | lo), transposed
__global__ void wconv_kernel(const float* __restrict__ W, __nv_bfloat16* __restrict__ Wt,
                             int K, int N) {
    __shared__ float t[64][33];
    int b = blockIdx.z;
    int k0 = blockIdx.y * 64, n0 = blockIdx.x * 32;
    int tx = threadIdx.x & 31, ty = threadIdx.x >> 5;
    const float* Wb = W + (size_t)b * K * N;
    #pragma unroll
    for (int q = 0; q < 8; q++) {
        int k = ty + q * 8;
        t[k][tx] = Wb[(size_t)(k0 + k) * N + n0 + tx];
    }
    __syncthreads();
    __nv_bfloat16* Wtb = Wt + (size_t)b * N * 2 * K;
    #pragma unroll
    for (int q = 0; q < 4; q++) {
        int n = ty + q * 8;
        int k = tx * 2;
        float v0 = t[k][n], v1 = t[k + 1][n];
        __nv_bfloat162 hh, ll;
        hh.x = __float2bfloat16(v0); hh.y = __float2bfloat16(v1);
        ll.x = __float2bfloat16(v0 - __bfloat162float(hh.x));
        ll.y = __float2bfloat16(v1 - __bfloat162float(hh.y));
        size_t base = (size_t)(n0 + n) * 2 * K;
        *(__nv_bfloat162*)(Wtb + base + k0 + k) = hh;
        *(__nv_bfloat162*)(Wtb + base + K + k0 + k) = ll;
    }
}

// ---------------- mma.sync split-bf16 GEMM ----------------
// C[128,128] fp32 = A @ B^T over 3 bf16 passes (hi*hi + lo*hi + hi*lo).
// A: [rows, 2*Ksrc] hi|lo ; B: [N, 2*Ksrc] hi|lo. K-chunk 64 bf16, 2-stage cp.async.
#define STAGE_BYTES 32768
#define GSMEM (2 * STAGE_BYTES + 1024)

__device__ __forceinline__ void gemm_issue_chunk(
    const __nv_bfloat16* __restrict__ A, int lda,
    const __nv_bfloat16* __restrict__ B, int ldb,
    int Ksrc, int kpc, int c, uint32_t sbase, int r0, int jel, int jby)
{
    int pass = 0, kb = c;
    if (kb >= kpc) { pass = 1; kb -= kpc; }
    if (kb >= kpc) { pass = 2; kb -= kpc; }
    int aoff = kb * 64 + (pass == 1 ? Ksrc : 0);
    int boff = kb * 64 + (pass == 2 ? Ksrc : 0);
    uint32_t bA = sbase + (uint32_t)(c & 1) * STAGE_BYTES;
    uint32_t bB = bA + 16384u;
    const __nv_bfloat16* pa = A + (size_t)r0 * lda + aoff + jel;
    const __nv_bfloat16* pb = B + (size_t)r0 * ldb + boff + jel;
    #pragma unroll
    for (int q = 0; q < 4; q++) {
        uint32_t so = swz((uint32_t)(r0 + q * 32) * 128u + (uint32_t)jby);
        CP16(bA + so, pa);
        CP16(bB + so, pb);
        pa += (size_t)32 * lda;
        pb += (size_t)32 * ldb;
    }
}

__device__ __forceinline__ void gemm3_core(
    const __nv_bfloat16* __restrict__ A, int lda,
    const __nv_bfloat16* __restrict__ B, int ldb,
    float* __restrict__ C, int ldc, int Ksrc, int mrem,
    const float* __restrict__ res)
{
    extern __shared__ __align__(16) char dsm[];
    uint32_t sbase = (smem_u32(dsm) + 1023u) & ~1023u;
    const int tid = threadIdx.x;
    const int wid = tid >> 5, lane = tid & 31;

    const int kpc = Ksrc >> 6;
    const int NC = 3 * kpc;
    const int jel = (tid & 7) * 8;
    const int jby = (tid & 7) * 16;
    const int r0 = tid >> 3;

    // warp tile: 2 warp-rows x 4 warp-cols, each 64x32
    const int m_warp = (wid & 1) * 64;
    const int n_warp = (wid >> 1) * 32;

    float acc[4][4][4];
    #pragma unroll
    for (int mt = 0; mt < 4; mt++)
        #pragma unroll
        for (int nt = 0; nt < 4; nt++)
            #pragma unroll
            for (int q = 0; q < 4; q++) acc[mt][nt][q] = 0.0f;

    gemm_issue_chunk(A, lda, B, ldb, Ksrc, kpc, 0, sbase, r0, jel, jby);
    CPCOMMIT();

    for (int i = 0; i < NC; i++) {
        if (i + 1 < NC) {
            gemm_issue_chunk(A, lda, B, ldb, Ksrc, kpc, i + 1, sbase, r0, jel, jby);
            CPCOMMIT();
            CPWAIT(1);
        } else {
            CPWAIT(0);
        }
        __syncthreads();

        uint32_t aA = sbase + (uint32_t)(i & 1) * STAGE_BYTES;
        uint32_t aB = aA + 16384u;
        #pragma unroll
        for (int ks = 0; ks < 4; ks++) {
            const uint32_t kb = (uint32_t)ks * 32u;
            uint32_t afr[4][4], bfr[4][2];
            #pragma unroll
            for (int mt = 0; mt < 4; mt++)
                ldmA(afr[mt], aA + swz((uint32_t)(m_warp + mt * 16 + (lane & 15)) * 128u
                                       + kb + (uint32_t)(lane >> 4) * 16u));
            #pragma unroll
            for (int nt = 0; nt < 4; nt++)
                ldmB(bfr[nt], aB + swz((uint32_t)(n_warp + nt * 8 + (lane & 7)) * 128u
                                       + kb + (uint32_t)((lane >> 3) & 1) * 16u));
            #pragma unroll
            for (int mt = 0; mt < 4; mt++)
                #pragma unroll
                for (int nt = 0; nt < 4; nt++)
                    mma_bf16(acc[mt][nt], afr[mt], bfr[nt]);
        }
        __syncthreads();
    }

    // epilogue
    #pragma unroll
    for (int mt = 0; mt < 4; mt++) {
        int rbase = m_warp + mt * 16 + (lane >> 2);
        #pragma unroll
        for (int half = 0; half < 2; half++) {
            int r = rbase + half * 8;
            if (r >= mrem) continue;
            float* crow = C + (size_t)r * ldc;
            const float* rrow = res ? res + (size_t)r * ldc : nullptr;
            #pragma unroll
            for (int nt = 0; nt < 4; nt++) {
                int c = n_warp + nt * 8 + (lane & 3) * 2;
                float2 v = make_float2(acc[mt][nt][half * 2], acc[mt][nt][half * 2 + 1]);
                if (rrow) {
                    float2 rv = *(const float2*)(rrow + c);
                    v.x += rv.x; v.y += rv.y;
                }
                *(float2*)(crow + c) = v;
            }
        }
    }
}

__global__ void __launch_bounds__(256, 2)
gemm_bf3(const __nv_bfloat16* __restrict__ A, int lda,
         const __nv_bfloat16* __restrict__ B, int ldb,
         float* __restrict__ C, int ldc, int Ksrc,
         const float* __restrict__ res) {
    int bx = blockIdx.x, by = blockIdx.y;
    gemm3_core(A + (size_t)by * 128 * lda, lda,
               B + (size_t)bx * 128 * ldb, ldb,
               C + (size_t)by * 128 * ldc + bx * 128, ldc, Ksrc, 128,
               res ? res + (size_t)by * 128 * ldc + bx * 128 : nullptr);
}

__global__ void __launch_bounds__(256, 2)
gemm_moe3(const __nv_bfloat16* __restrict__ A, int lda,
          const __nv_bfloat16* __restrict__ Ball, int ldb, long long strideB,
          float* __restrict__ C, int ldc, int Ksrc) {
    int e = blockIdx.z;
    int cnt = g_cnt[e];
    int by = blockIdx.y, bx = blockIdx.x;
    if (by * 128 >= cnt) return;
    int off = g_off[e];
    gemm3_core(A + (size_t)(off + by * 128) * lda, lda,
               Ball + (size_t)e * strideB + (size_t)bx * 128 * ldb, ldb,
               C + (size_t)(off + by * 128) * ldc + bx * 128, ldc, Ksrc,
               cnt - by * 128, nullptr);
}

// ---------------- flash attention (fp32, bf16 hi|lo output) ----------------
#define ATTN_SMEM ((64*64 + 64*65 + 64*68 + 64*68) * 4)

__global__ void attn_kernel(const float* __restrict__ qkv,
                            const float* __restrict__ mask,
                            __nv_bfloat16* __restrict__ outbf) {
    extern __shared__ float sm[];
    float* Qs = sm;
    float* Kt = Qs + 64 * 64;
    float* Vs = Kt + 64 * 65;
    float* Ps = Vs + 64 * 68;

    const int tid = threadIdx.x;
    const int qb = blockIdx.x;
    const int bh = blockIdx.y;
    const int b = bh >> 4, h = bh & 15;
    const int s0 = qb * 64;
    const int tx = tid & 15, ty = tid >> 4;

    for (int idx = tid; idx < 64 * 16; idx += 256) {
        int r = idx >> 4, c4 = (idx & 15) << 2;
        float4 v = *(const float4*)(qkv + (size_t)(b * SEQ + s0 + r) * TQKV + h * HD + c4);
        v.x *= 0.125f; v.y *= 0.125f; v.z *= 0.125f; v.w *= 0.125f;
        *(float4*)(Qs + r * 64 + c4) = v;
    }

    float m[4], l[4], o[4][4];
    #pragma unroll
    for (int i = 0; i < 4; i++) {
        m[i] = -3.0e38f; l[i] = 0.0f;
        #pragma unroll
        for (int j = 0; j < 4; j++) o[i][j] = 0.0f;
    }

    for (int kt = 0; kt < SEQ / 64; kt++) {
        __syncthreads();
        const int k0 = kt * 64;
        for (int idx = tid; idx < 64 * 16; idx += 256) {
            int r = idx >> 4, c4 = (idx & 15) << 2;
            const float* src = qkv + (size_t)(b * SEQ + k0 + r) * TQKV + NH * HD + h * HD + c4;
            float4 kv = *(const float4*)src;
            Kt[(c4 + 0) * 65 + r] = kv.x;
            Kt[(c4 + 1) * 65 + r] = kv.y;
            Kt[(c4 + 2) * 65 + r] = kv.z;
            Kt[(c4 + 3) * 65 + r] = kv.w;
            float4 vv = *(const float4*)(src + NH * HD);
            *(float4*)(Vs + r * 68 + c4) = vv;
        }
        __syncthreads();

        float sv[4][4];
        #pragma unroll
        for (int i = 0; i < 4; i++) {
            float4 mk = *(const float4*)(mask + (size_t)(s0 + ty * 4 + i) * SEQ + k0 + tx * 4);
            sv[i][0] = mk.x; sv[i][1] = mk.y; sv[i][2] = mk.z; sv[i][3] = mk.w;
        }
        #pragma unroll 8
        for (int kk = 0; kk < 64; kk++) {
            float qf[4], kf[4];
            #pragma unroll
            for (int i = 0; i < 4; i++) qf[i] = Qs[(ty * 4 + i) * 64 + kk];
            #pragma unroll
            for (int j = 0; j < 4; j++) kf[j] = Kt[kk * 65 + tx * 4 + j];
            #pragma unroll
            for (int i = 0; i < 4; i++)
                #pragma unroll
                for (int j = 0; j < 4; j++)
                    sv[i][j] = fmaf(qf[i], kf[j], sv[i][j]);
        }

        #pragma unroll
        for (int i = 0; i < 4; i++) {
            float tm = fmaxf(fmaxf(sv[i][0], sv[i][1]), fmaxf(sv[i][2], sv[i][3]));
            #pragma unroll
            for (int off = 1; off < 16; off <<= 1)
                tm = fmaxf(tm, __shfl_xor_sync(0xffffffffu, tm, off));
            float mn = fmaxf(m[i], tm);
            float corr = __expf(m[i] - mn);
            float rs = 0.0f;
            #pragma unroll
            for (int j = 0; j < 4; j++) {
                float p = __expf(sv[i][j] - mn);
                sv[i][j] = p; rs += p;
            }
            #pragma unroll
            for (int off = 1; off < 16; off <<= 1)
                rs += __shfl_xor_sync(0xffffffffu, rs, off);
            l[i] = l[i] * corr + rs;
            m[i] = mn;
            #pragma unroll
            for (int j = 0; j < 4; j++) o[i][j] *= corr;
            *(float4*)(Ps + (ty * 4 + i) * 68 + tx * 4) =
                make_float4(sv[i][0], sv[i][1], sv[i][2], sv[i][3]);
        }
        __syncthreads();

        #pragma unroll 8
        for (int kk = 0; kk < 64; kk++) {
            float pf[4];
            #pragma unroll
            for (int i = 0; i < 4; i++) pf[i] = Ps[(ty * 4 + i) * 68 + kk];
            float4 vv = *(const float4*)(Vs + kk * 68 + tx * 4);
            #pragma unroll
            for (int i = 0; i < 4; i++) {
                o[i][0] = fmaf(pf[i], vv.x, o[i][0]);
                o[i][1] = fmaf(pf[i], vv.y, o[i][1]);
                o[i][2] = fmaf(pf[i], vv.z, o[i][2]);
                o[i][3] = fmaf(pf[i], vv.w, o[i][3]);
            }
        }
    }

    #pragma unroll
    for (int i = 0; i < 4; i++) {
        float inv = 1.0f / l[i];
        float4 r = make_float4(o[i][0] * inv, o[i][1] * inv, o[i][2] * inv, o[i][3] * inv);
        size_t row = (size_t)(b * SEQ + s0 + ty * 4 + i);
        store_hilo4(outbf + row * 2 * HDIM + h * HD + tx * 4,
                    outbf + row * 2 * HDIM + HDIM + h * HD + tx * 4, r);
    }
}

// ---------------- routing ----------------
__global__ void router_kernel(const float* __restrict__ hf, const float* __restrict__ rw) {
    int t = blockIdx.x, tid = threadIdx.x;
    int w = tid >> 5, lane = tid & 31;
    __shared__ float logits[NE];
    float s = 0.0f;
    for (int i = lane; i < HDIM; i += 32)
        s += hf[(size_t)t * HDIM + i] * __ldg(rw + (size_t)i * NE + w);
    #pragma unroll
    for (int o = 16; o; o >>= 1) s += __shfl_xor_sync(0xffffffffu, s, o);
    if (lane == 0) logits[w] = s;
    __syncthreads();
    if (tid == 0) {
        int e0 = 0; float b0 = logits[0];
        #pragma unroll
        for (int e = 1; e < NE; e++) if (logits[e] > b0) { b0 = logits[e]; e0 = e; }
        int e1 = -1; float b1 = -3.0e38f;
        #pragma unroll
        for (int e = 0; e < NE; e++)
            if (e != e0 && logits[e] > b1) { b1 = logits[e]; e1 = e; }
        float w0 = 1.0f / (1.0f + expf(b1 - b0));
        g_tok_e[t * 2 + 0] = e0;
        g_tok_e[t * 2 + 1] = e1;
        g_tok_w[t * 2 + 0] = w0;
        g_tok_w[t * 2 + 1] = 1.0f - w0;
        atomicAdd(&g_cnt[e0], 1);
        atomicAdd(&g_cnt[e1], 1);
    }
}

__global__ void scan_kernel() {
    if (threadIdx.x == 0) {
        int acc = 0;
        for (int e = 0; e < NE; e++) { g_off[e] = acc; acc += g_cnt[e]; g_cur[e] = 0; }
    }
}

__global__ void assign_gather_kernel(const float* __restrict__ hf) {
    int t = blockIdx.x, tid = threadIdx.x;
    __shared__ int sl[2];
    if (tid < 2) {
        int e = g_tok_e[t * 2 + tid];
        int s = g_off[e] + atomicAdd(&g_cur[e], 1);
        sl[tid] = s;
        g_tok_slot[t * 2 + tid] = s;
    }
    __syncthreads();
    float4 v = ((const float4*)(hf + (size_t)t * HDIM))[tid];
    #pragma unroll
    for (int k = 0; k < 2; k++) {
        __nv_bfloat16* base = g_xgbf + (size_t)sl[k] * 2 * HDIM;
        store_hilo4(base + tid * 4, base + HDIM + tid * 4, v);
    }
}

__global__ void silu_kernel() {
    size_t idx = (size_t)blockIdx.x * 256 + threadIdx.x;
    int row = (int)(idx >> 9);
    int jj = (int)(idx & 511) << 2;
    const float* g = g_gu + (size_t)row * (2 * INTER) + jj;
    float4 gv = *(const float4*)g;
    float4 uv = *(const float4*)(g + INTER);
    float4 r;
    r.x = gv.x / (1.0f + __expf(-gv.x)) * uv.x;
    r.y = gv.y / (1.0f + __expf(-gv.y)) * uv.y;
    r.z = gv.z / (1.0f + __expf(-gv.z)) * uv.z;
    r.w = gv.w / (1.0f + __expf(-gv.w)) * uv.w;
    __nv_bfloat16* base = g_actbf + (size_t)row * 2 * INTER;
    store_hilo4(base + jj, base + INTER + jj, r);
}

__global__ void combine_kernel(float* __restrict__ out) {
    int t = blockIdx.x, tid = threadIdx.x;
    int s0 = g_tok_slot[t * 2 + 0], s1 = g_tok_slot[t * 2 + 1];
    float w0 = g_tok_w[t * 2 + 0], w1 = g_tok_w[t * 2 + 1];
    float4 x = ((float4*)(out + (size_t)t * HDIM))[tid];
    float4 a = ((const float4*)(g_dn + (size_t)s0 * HDIM))[tid];
    float4 b = ((const float4*)(g_dn + (size_t)s1 * HDIM))[tid];
    x.x += w0 * a.x + w1 * b.x;
    x.y += w0 * a.y + w1 * b.y;
    x.z += w0 * a.z + w1 * b.z;
    x.w += w0 * a.w + w1 * b.w;
    ((float4*)(out + (size_t)t * HDIM))[tid] = x;
}

// ---------------- launch ----------------
extern "C" void kernel_launch(void* const* d_in, const int* in_sizes, int n_in,
                              void* d_out, int out_size) {
    const float* hidden = (const float*)d_in[0];
    const float* mask   = (const float*)d_in[1];
    const float* ln1    = (const float*)d_in[2];
    const float* ln2    = (const float*)d_in[3];
    const float* qkv_w  = (const float*)d_in[4];
    const float* o_w    = (const float*)d_in[5];
    const float* rt_w   = (const float*)d_in[6];
    const float* gup    = (const float*)d_in[7];
    const float* dwn    = (const float*)d_in[8];
    float* out = (float*)d_out;

    float *qkvb, *hfb, *gu, *dn;
    __nv_bfloat16 *hnbf, *attnbf, *xgbf, *actbf, *qkvwt, *owt, *gupt, *dwnt;
    cudaGetSymbolAddress((void**)&qkvb,  g_qkv);
    cudaGetSymbolAddress((void**)&hfb,   g_hf);
    cudaGetSymbolAddress((void**)&gu,    g_gu);
    cudaGetSymbolAddress((void**)&dn,    g_dn);
    cudaGetSymbolAddress((void**)&hnbf,  g_hnbf);
    cudaGetSymbolAddress((void**)&attnbf, g_attnbf);
    cudaGetSymbolAddress((void**)&xgbf,  g_xgbf);
    cudaGetSymbolAddress((void**)&actbf, g_actbf);
    cudaGetSymbolAddress((void**)&qkvwt, g_qkvwt);
    cudaGetSymbolAddress((void**)&owt,   g_owt);
    cudaGetSymbolAddress((void**)&gupt,  g_gupt);
    cudaGetSymbolAddress((void**)&dwnt,  g_dwnt);

    cudaFuncSetAttribute(attn_kernel, cudaFuncAttributeMaxDynamicSharedMemorySize, ATTN_SMEM);
    cudaFuncSetAttribute(gemm_bf3, cudaFuncAttributeMaxDynamicSharedMemorySize, GSMEM);
    cudaFuncSetAttribute(gemm_moe3, cudaFuncAttributeMaxDynamicSharedMemorySize, GSMEM);

    zero_kernel<<<1, 32>>>();

    // weight transpose + hi/lo split
    wconv_kernel<<<dim3(TQKV / 32, HDIM / 64, 1), 256>>>(qkv_w, qkvwt, HDIM, TQKV);
    wconv_kernel<<<dim3(HDIM / 32, HDIM / 64, 1), 256>>>(o_w, owt, HDIM, HDIM);
    wconv_kernel<<<dim3(2 * INTER / 32, HDIM / 64, NE), 256>>>(gup, gupt, HDIM, 2 * INTER);
    wconv_kernel<<<dim3(HDIM / 32, INTER / 64, NE), 256>>>(dwn, dwnt, INTER, HDIM);

    // attention block
    rmsnorm_kernel<<<NTOK, 256>>>(hidden, ln1, nullptr, hnbf);
    gemm_bf3<<<dim3(TQKV / 128, NTOK / 128), 256, GSMEM>>>(
        hnbf, 2 * HDIM, qkvwt, 2 * HDIM, qkvb, TQKV, HDIM, nullptr);
    attn_kernel<<<dim3(SEQ / 64, NBATCH * NH), 256, ATTN_SMEM>>>(qkvb, mask, attnbf);
    gemm_bf3<<<dim3(HDIM / 128, NTOK / 128), 256, GSMEM>>>(
        attnbf, 2 * HDIM, owt, 2 * HDIM, out, HDIM, HDIM, hidden);

    // moe block
    rmsnorm_kernel<<<NTOK, 256>>>(out, ln2, hfb, nullptr);
    router_kernel<<<NTOK, 256>>>(hfb, rt_w);
    scan_kernel<<<1, 32>>>();
    assign_gather_kernel<<<NTOK, 256>>>(hfb);

    gemm_moe3<<<dim3(2 * INTER / 128, NTOK / 128, NE), 256, GSMEM>>>(
        xgbf, 2 * HDIM, gupt, 2 * HDIM, (long long)(2 * INTER) * 2 * HDIM,
        gu, 2 * INTER, HDIM);
    silu_kernel<<<(SLOTS * (INTER / 4)) / 256, 256>>>();
    gemm_moe3<<<dim3(HDIM / 128, NTOK / 128, NE), 256, GSMEM>>>(
        actbf, 2 * INTER, dwnt, 2 * INTER, (long long)HDIM * 2 * INTER,
        dn, HDIM, INTER);

    combine_kernel<<<NTOK, 256>>>(out);
}

// round 7
// speedup vs baseline: 4.4093x; 1.2368x over previous
#include <cuda_runtime.h>
#include <cuda_bf16.h>
#include <math.h>
#include <stdint.h>

// ---------------- problem constants ----------------
#define HDIM   1024
#define NH     16
#define HD     64
#define INTER  2048
#define NE     8
#define SEQ    1024
#define NBATCH 4
#define NTOK   4096
#define TQKV   3072
#define SLOTS  8192

// ---------------- scratch ----------------
__device__ float g_hf[(size_t)NTOK * HDIM];
__device__ float g_gu[(size_t)SLOTS * 2 * INTER];
__device__ float g_dn[(size_t)SLOTS * HDIM];

__device__ __nv_bfloat16 g_qkvbf[(size_t)NTOK * 2 * TQKV];         // qkv hi|lo
__device__ __nv_bfloat16 g_hnbf[(size_t)NTOK * 2 * HDIM];
__device__ __nv_bfloat16 g_attnbf[(size_t)NTOK * 2 * HDIM];
__device__ __nv_bfloat16 g_xgbf[(size_t)(SLOTS + 128) * 2 * HDIM];
__device__ __nv_bfloat16 g_actbf[(size_t)(SLOTS + 128) * 2 * INTER];

__device__ __nv_bfloat16 g_qkvwt[(size_t)TQKV * 2 * HDIM];
__device__ __nv_bfloat16 g_owt[(size_t)HDIM * 2 * HDIM];
__device__ __nv_bfloat16 g_gupt[(size_t)NE * 2 * INTER * 2 * HDIM];
__device__ __nv_bfloat16 g_dwnt[(size_t)NE * HDIM * 2 * INTER];

__device__ int   g_cnt[NE];
__device__ int   g_off[NE];
__device__ int   g_cur[NE];
__device__ int   g_tok_e[NTOK * 2];
__device__ int   g_tok_slot[NTOK * 2];
__device__ float g_tok_w[NTOK * 2];

// ---------------- PTX helpers ----------------
__device__ __forceinline__ uint32_t smem_u32(const void* p) {
    uint32_t a;
    asm("{ .reg .u64 t; cvta.to.shared.u64 t, %1; cvt.u32.u64 %0, t; }" : "=r"(a) : "l"(p));
    return a;
}
#define CP16(dst, src) asm volatile("cp.async.cg.shared.global [%0], [%1], 16;\n" :: "r"(dst), "l"(src) : "memory")
#define CPCOMMIT()     asm volatile("cp.async.commit_group;\n" ::: "memory")
#define CPWAIT(n)      asm volatile("cp.async.wait_group %0;\n" :: "n"(n) : "memory")

__device__ __forceinline__ void ldm4(uint32_t* a, uint32_t addr) {
    asm volatile("ldmatrix.sync.aligned.m8n8.x4.shared.b16 {%0,%1,%2,%3},[%4];"
        : "=r"(a[0]), "=r"(a[1]), "=r"(a[2]), "=r"(a[3]) : "r"(addr));
}
__device__ __forceinline__ void ldm4t(uint32_t* a, uint32_t addr) {
    asm volatile("ldmatrix.sync.aligned.m8n8.x4.trans.shared.b16 {%0,%1,%2,%3},[%4];"
        : "=r"(a[0]), "=r"(a[1]), "=r"(a[2]), "=r"(a[3]) : "r"(addr));
}
__device__ __forceinline__ void ldmB(uint32_t* b, uint32_t addr) {
    asm volatile("ldmatrix.sync.aligned.m8n8.x2.shared.b16 {%0,%1},[%2];"
        : "=r"(b[0]), "=r"(b[1]) : "r"(addr));
}
__device__ __forceinline__ void mma_bf16(float* d, const uint32_t* a, const uint32_t* b) {
    asm volatile("mma.sync.aligned.m16n8k16.row.col.f32.bf16.bf16.f32 "
                 "{%0,%1,%2,%3},{%4,%5,%6,%7},{%8,%9},{%0,%1,%2,%3};"
        : "+f"(d[0]), "+f"(d[1]), "+f"(d[2]), "+f"(d[3])
        : "r"(a[0]), "r"(a[1]), "r"(a[2]), "r"(a[3]), "r"(b[0]), "r"(b[1]));
}

__device__ __forceinline__ uint32_t swz(uint32_t o) { return o ^ ((o >> 3) & 0x70); }

// ---------------- hi/lo split helpers ----------------
__device__ __forceinline__ void store_hilo4(__nv_bfloat16* hip, __nv_bfloat16* lop, float4 v) {
    __nv_bfloat162 h0, h1, l0, l1;
    h0.x = __float2bfloat16(v.x); h0.y = __float2bfloat16(v.y);
    h1.x = __float2bfloat16(v.z); h1.y = __float2bfloat16(v.w);
    l0.x = __float2bfloat16(v.x - __bfloat162float(h0.x));
    l0.y = __float2bfloat16(v.y - __bfloat162float(h0.y));
    l1.x = __float2bfloat16(v.z - __bfloat162float(h1.x));
    l1.y = __float2bfloat16(v.w - __bfloat162float(h1.y));
    *(__nv_bfloat162*)hip = h0; *(__nv_bfloat162*)(hip + 2) = h1;
    *(__nv_bfloat162*)lop = l0; *(__nv_bfloat162*)(lop + 2) = l1;
}
__device__ __forceinline__ void store_hilo2(__nv_bfloat16* hip, __nv_bfloat16* lop, float2 v) {
    __nv_bfloat162 h, l;
    h.x = __float2bfloat16(v.x); h.y = __float2bfloat16(v.y);
    l.x = __float2bfloat16(v.x - __bfloat162float(h.x));
    l.y = __float2bfloat16(v.y - __bfloat162float(h.y));
    *(__nv_bfloat162*)hip = h; *(__nv_bfloat162*)lop = l;
}
__device__ __forceinline__ uint32_t pack_bf2(float x, float y) {
    __nv_bfloat162 h;
    h.x = __float2bfloat16(x); h.y = __float2bfloat16(y);
    return *(uint32_t*)&h;
}

// ---------------- small kernels ----------------
__global__ void zero_kernel() { if (threadIdx.x < NE) g_cnt[threadIdx.x] = 0; }

__global__ void rmsnorm_kernel(const float* __restrict__ x, const float* __restrict__ w,
                               float* __restrict__ yf, __nv_bfloat16* __restrict__ yb) {
    int t = blockIdx.x, tid = threadIdx.x;
    const float4 v = ((const float4*)(x + (size_t)t * HDIM))[tid];
    float ss = v.x * v.x + v.y * v.y + v.z * v.z + v.w * v.w;
    __shared__ float red[8];
    #pragma unroll
    for (int o = 16; o; o >>= 1) ss += __shfl_xor_sync(0xffffffffu, ss, o);
    if ((tid & 31) == 0) red[tid >> 5] = ss;
    __syncthreads();
    if (tid < 8) {
        float s2 = red[tid];
        #pragma unroll
        for (int o = 4; o; o >>= 1) s2 += __shfl_xor_sync(0xffu, s2, o);
        if (tid == 0) red[0] = s2;
    }
    __syncthreads();
    float inv = rsqrtf(red[0] * (1.0f / HDIM) + 1e-6f);
    const float4 wv = ((const float4*)w)[tid];
    float4 r = make_float4(v.x * inv * wv.x, v.y * inv * wv.y,
                           v.z * inv * wv.z, v.w * inv * wv.w);
    if (yf) ((float4*)(yf + (size_t)t * HDIM))[tid] = r;
    if (yb) store_hilo4(yb + (size_t)t * 2 * HDIM + tid * 4,
                        yb + (size_t)t * 2 * HDIM + HDIM + tid * 4, r);
}

// W[b][K][N] fp32 -> Wt[b][N][2K] bf16 (hi | lo), transposed
__global__ void wconv_kernel(const float* __restrict__ W, __nv_bfloat16* __restrict__ Wt,
                             int K, int N) {
    __shared__ float t[64][33];
    int b = blockIdx.z;
    int k0 = blockIdx.y * 64, n0 = blockIdx.x * 32;
    int tx = threadIdx.x & 31, ty = threadIdx.x >> 5;
    const float* Wb = W + (size_t)b * K * N;
    #pragma unroll
    for (int q = 0; q < 8; q++) {
        int k = ty + q * 8;
        t[k][tx] = Wb[(size_t)(k0 + k) * N + n0 + tx];
    }
    __syncthreads();
    __nv_bfloat16* Wtb = Wt + (size_t)b * N * 2 * K;
    #pragma unroll
    for (int q = 0; q < 4; q++) {
        int n = ty + q * 8;
        int k = tx * 2;
        float v0 = t[k][n], v1 = t[k + 1][n];
        __nv_bfloat162 hh, ll;
        hh.x = __float2bfloat16(v0); hh.y = __float2bfloat16(v1);
        ll.x = __float2bfloat16(v0 - __bfloat162float(hh.x));
        ll.y = __float2bfloat16(v1 - __bfloat162float(hh.y));
        size_t base = (size_t)(n0 + n) * 2 * K;
        *(__nv_bfloat162*)(Wtb + base + k0 + k) = hh;
        *(__nv_bfloat162*)(Wtb + base + K + k0 + k) = ll;
    }
}

// ---------------- mma.sync split-bf16 GEMM ----------------
#define STAGE_BYTES 32768
#define GSMEM (2 * STAGE_BYTES + 1024)

__device__ __forceinline__ void gemm_issue_chunk(
    const __nv_bfloat16* __restrict__ A, int lda,
    const __nv_bfloat16* __restrict__ B, int ldb,
    int Ksrc, int kpc, int c, uint32_t sbase, int r0, int jel, int jby)
{
    int pass = 0, kb = c;
    if (kb >= kpc) { pass = 1; kb -= kpc; }
    if (kb >= kpc) { pass = 2; kb -= kpc; }
    int aoff = kb * 64 + (pass == 1 ? Ksrc : 0);
    int boff = kb * 64 + (pass == 2 ? Ksrc : 0);
    uint32_t bA = sbase + (uint32_t)(c & 1) * STAGE_BYTES;
    uint32_t bB = bA + 16384u;
    const __nv_bfloat16* pa = A + (size_t)r0 * lda + aoff + jel;
    const __nv_bfloat16* pb = B + (size_t)r0 * ldb + boff + jel;
    #pragma unroll
    for (int q = 0; q < 4; q++) {
        uint32_t so = swz((uint32_t)(r0 + q * 32) * 128u + (uint32_t)jby);
        CP16(bA + so, pa);
        CP16(bB + so, pb);
        pa += (size_t)32 * lda;
        pb += (size_t)32 * ldb;
    }
}

__device__ __forceinline__ void gemm3_core(
    const __nv_bfloat16* __restrict__ A, int lda,
    const __nv_bfloat16* __restrict__ B, int ldb,
    float* __restrict__ C, int ldc, int Ksrc, int mrem,
    const float* __restrict__ res,
    __nv_bfloat16* __restrict__ Cbf, int ldcb, int bfoff)
{
    extern __shared__ __align__(16) char dsm[];
    uint32_t sbase = (smem_u32(dsm) + 1023u) & ~1023u;
    const int tid = threadIdx.x;
    const int wid = tid >> 5, lane = tid & 31;

    const int kpc = Ksrc >> 6;
    const int NC = 3 * kpc;
    const int jel = (tid & 7) * 8;
    const int jby = (tid & 7) * 16;
    const int r0 = tid >> 3;

    const int m_warp = (wid & 1) * 64;
    const int n_warp = (wid >> 1) * 32;

    float acc[4][4][4];
    #pragma unroll
    for (int mt = 0; mt < 4; mt++)
        #pragma unroll
        for (int nt = 0; nt < 4; nt++)
            #pragma unroll
            for (int q = 0; q < 4; q++) acc[mt][nt][q] = 0.0f;

    gemm_issue_chunk(A, lda, B, ldb, Ksrc, kpc, 0, sbase, r0, jel, jby);
    CPCOMMIT();

    for (int i = 0; i < NC; i++) {
        if (i + 1 < NC) {
            gemm_issue_chunk(A, lda, B, ldb, Ksrc, kpc, i + 1, sbase, r0, jel, jby);
            CPCOMMIT();
            CPWAIT(1);
        } else {
            CPWAIT(0);
        }
        __syncthreads();

        uint32_t aA = sbase + (uint32_t)(i & 1) * STAGE_BYTES;
        uint32_t aB = aA + 16384u;
        #pragma unroll
        for (int ks = 0; ks < 4; ks++) {
            const uint32_t kb = (uint32_t)ks * 32u;
            uint32_t afr[4][4], bfr[4][2];
            #pragma unroll
            for (int mt = 0; mt < 4; mt++)
                ldm4(afr[mt], aA + swz((uint32_t)(m_warp + mt * 16 + (lane & 15)) * 128u
                                       + kb + (uint32_t)(lane >> 4) * 16u));
            #pragma unroll
            for (int nt = 0; nt < 4; nt++)
                ldmB(bfr[nt], aB + swz((uint32_t)(n_warp + nt * 8 + (lane & 7)) * 128u
                                       + kb + (uint32_t)((lane >> 3) & 1) * 16u));
            #pragma unroll
            for (int mt = 0; mt < 4; mt++)
                #pragma unroll
                for (int nt = 0; nt < 4; nt++)
                    mma_bf16(acc[mt][nt], afr[mt], bfr[nt]);
        }
        __syncthreads();
    }

    #pragma unroll
    for (int mt = 0; mt < 4; mt++) {
        int rbase = m_warp + mt * 16 + (lane >> 2);
        #pragma unroll
        for (int half = 0; half < 2; half++) {
            int r = rbase + half * 8;
            if (r >= mrem) continue;
            #pragma unroll
            for (int nt = 0; nt < 4; nt++) {
                int c = n_warp + nt * 8 + (lane & 3) * 2;
                float2 v = make_float2(acc[mt][nt][half * 2], acc[mt][nt][half * 2 + 1]);
                if (Cbf) {
                    store_hilo2(Cbf + (size_t)r * ldcb + c,
                                Cbf + (size_t)r * ldcb + bfoff + c, v);
                } else {
                    if (res) {
                        float2 rv = *(const float2*)(res + (size_t)r * ldc + c);
                        v.x += rv.x; v.y += rv.y;
                    }
                    *(float2*)(C + (size_t)r * ldc + c) = v;
                }
            }
        }
    }
}

__global__ void __launch_bounds__(256, 2)
gemm_bf3(const __nv_bfloat16* __restrict__ A, int lda,
         const __nv_bfloat16* __restrict__ B, int ldb,
         float* __restrict__ C, int ldc, int Ksrc,
         const float* __restrict__ res,
         __nv_bfloat16* __restrict__ Cbf, int ldcb, int bfoff) {
    int bx = blockIdx.x, by = blockIdx.y;
    float* Cp = C ? C + (size_t)by * 128 * ldc + bx * 128 : nullptr;
    const float* rp = res ? res + (size_t)by * 128 * ldc + bx * 128 : nullptr;
    __nv_bfloat16* Cbp = Cbf ? Cbf + (size_t)by * 128 * ldcb + bx * 128 : nullptr;
    gemm3_core(A + (size_t)by * 128 * lda, lda,
               B + (size_t)bx * 128 * ldb, ldb,
               Cp, ldc, Ksrc, 128, rp, Cbp, ldcb, bfoff);
}

__global__ void __launch_bounds__(256, 2)
gemm_moe3(const __nv_bfloat16* __restrict__ A, int lda,
          const __nv_bfloat16* __restrict__ Ball, int ldb, long long strideB,
          float* __restrict__ C, int ldc, int Ksrc) {
    int e = blockIdx.z;
    int cnt = g_cnt[e];
    int by = blockIdx.y, bx = blockIdx.x;
    if (by * 128 >= cnt) return;
    int off = g_off[e];
    gemm3_core(A + (size_t)(off + by * 128) * lda, lda,
               Ball + (size_t)e * strideB + (size_t)bx * 128 * ldb, ldb,
               C + (size_t)(off + by * 128) * ldc + bx * 128, ldc, Ksrc,
               cnt - by * 128, nullptr, nullptr, 0, 0);
}

// ---------------- tensor-core flash attention ----------------
// grid (SEQ/128, NBATCH*NH), 256 threads (8 warps x 16 q-rows).
// S = QK^T: 3-pass hi/lo bf16 mma. softmax fp32. O += P(hi) * V(hi+lo).
#define ANT (SEQ / 64)            // 16 k-tiles
#define ATTN2_SMEM (96 * 1024 + 1024)

__global__ void __launch_bounds__(256, 1)
attn_mma_kernel(const __nv_bfloat16* __restrict__ qkvbf,
                const float* __restrict__ mask,
                __nv_bfloat16* __restrict__ outbf) {
    extern __shared__ char asmem[];
    const uint32_t sb = (smem_u32(asmem) + 1023u) & ~1023u;
    const uint32_t QH = sb, QL = sb + 16384u;   // Q 128x64 hi/lo
    // stages at sb+32768 + st*32768 : [KH 0][KL 8192][VH 16384][VL 24576]
    const int tid = threadIdx.x, lane = tid & 31, wid = tid >> 5;
    const int bh = blockIdx.y, b = bh >> 4, h = bh & 15;
    const int s0 = blockIdx.x * 128;
    const int m_warp = wid * 16;

    const int r0 = tid >> 3;
    const int jel = (tid & 7) * 8;
    const uint32_t jby = (uint32_t)(tid & 7) * 16u;

    // Q load (group 0, together with KV stage 0)
    {
        const __nv_bfloat16* src = qkvbf + (size_t)(b * SEQ + s0 + r0) * (2 * TQKV) + h * HD + jel;
        #pragma unroll
        for (int q = 0; q < 4; q++) {
            uint32_t so = swz((uint32_t)(r0 + q * 32) * 128u + jby);
            CP16(QH + so, src);
            CP16(QL + so, src + TQKV);
            src += (size_t)32 * (2 * TQKV);
        }
    }
    auto load_kv = [&](int kt, int st) {
        uint32_t base = sb + 32768u + (uint32_t)st * 32768u;
        const __nv_bfloat16* src = qkvbf + (size_t)(b * SEQ + kt * 64 + r0) * (2 * TQKV)
                                   + NH * HD + h * HD + jel;
        #pragma unroll
        for (int q = 0; q < 2; q++) {
            uint32_t so = swz((uint32_t)(r0 + q * 32) * 128u + jby);
            CP16(base + so,          src);                     // K hi
            CP16(base + 8192u + so,  src + TQKV);              // K lo
            CP16(base + 16384u + so, src + NH * HD);           // V hi
            CP16(base + 24576u + so, src + TQKV + NH * HD);    // V lo
            src += (size_t)32 * (2 * TQKV);
        }
    };
    load_kv(0, 0);
    CPCOMMIT();

    float mrow[2] = {-3.0e38f, -3.0e38f}, lrow[2] = {0.0f, 0.0f};
    float o[8][4];
    #pragma unroll
    for (int nt = 0; nt < 8; nt++)
        #pragma unroll
        for (int q = 0; q < 4; q++) o[nt][q] = 0.0f;

    uint32_t qhi[4][4], qlo[4][4];

    for (int kt = 0; kt < ANT; kt++) {
        if (kt + 1 < ANT) {
            load_kv(kt + 1, (kt + 1) & 1);
            CPCOMMIT();
            CPWAIT(1);
        } else {
            CPWAIT(0);
        }
        __syncthreads();

        if (kt == 0) {
            #pragma unroll
            for (int ks = 0; ks < 4; ks++) {
                uint32_t ao = swz((uint32_t)(m_warp + (lane & 15)) * 128u
                                  + (uint32_t)ks * 32u + (uint32_t)(lane >> 4) * 16u);
                ldm4(qhi[ks], QH + ao);
                ldm4(qlo[ks], QL + ao);
            }
        }

        const uint32_t KB = sb + 32768u + (uint32_t)(kt & 1) * 32768u;
        const uint32_t VB = KB + 16384u;

        // ---- S = Q K^T (3-pass split) ----
        float sv[8][4];
        #pragma unroll
        for (int nt = 0; nt < 8; nt++)
            #pragma unroll
            for (int q = 0; q < 4; q++) sv[nt][q] = 0.0f;

        #pragma unroll
        for (int ks = 0; ks < 4; ks++) {
            uint32_t kh[16], kl[16];
            #pragma unroll
            for (int np = 0; np < 4; np++) {
                uint32_t ro = swz((uint32_t)(np * 16 + (lane & 7) + ((lane >> 4) << 3)) * 128u
                                  + (uint32_t)ks * 32u + (uint32_t)((lane >> 3) & 1) * 16u);
                ldm4(&kh[np * 4], KB + ro);
                ldm4(&kl[np * 4], KB + 8192u + ro);
            }
            #pragma unroll
            for (int nt = 0; nt < 8; nt++) {
                mma_bf16(sv[nt], qhi[ks], &kh[nt * 2]);
                mma_bf16(sv[nt], qlo[ks], &kh[nt * 2]);
                mma_bf16(sv[nt], qhi[ks], &kl[nt * 2]);
            }
        }

        // ---- scale + mask + online softmax ----
        const float* mbase = mask + (size_t)(s0 + m_warp + (lane >> 2)) * SEQ
                             + kt * 64 + (lane & 3) * 2;
        #pragma unroll
        for (int half = 0; half < 2; half++) {
            const float* mp = mbase + (size_t)half * 8 * SEQ;
            float tmax = -3.0e38f;
            #pragma unroll
            for (int nt = 0; nt < 8; nt++) {
                float2 mk = *(const float2*)(mp + nt * 8);
                float a = sv[nt][half * 2]     * 0.125f + mk.x;
                float bb = sv[nt][half * 2 + 1] * 0.125f + mk.y;
                sv[nt][half * 2] = a; sv[nt][half * 2 + 1] = bb;
                tmax = fmaxf(tmax, fmaxf(a, bb));
            }
            tmax = fmaxf(tmax, __shfl_xor_sync(0xffffffffu, tmax, 1));
            tmax = fmaxf(tmax, __shfl_xor_sync(0xffffffffu, tmax, 2));
            float mn = fmaxf(mrow[half], tmax);
            float corr = __expf(mrow[half] - mn);
            float rs = 0.0f;
            #pragma unroll
            for (int nt = 0; nt < 8; nt++) {
                float p0 = __expf(sv[nt][half * 2] - mn);
                float p1 = __expf(sv[nt][half * 2 + 1] - mn);
                sv[nt][half * 2] = p0; sv[nt][half * 2 + 1] = p1;
                rs += p0 + p1;
            }
            rs += __shfl_xor_sync(0xffffffffu, rs, 1);
            rs += __shfl_xor_sync(0xffffffffu, rs, 2);
            lrow[half] = lrow[half] * corr + rs;
            mrow[half] = mn;
            #pragma unroll
            for (int nt = 0; nt < 8; nt++) {
                o[nt][half * 2] *= corr;
                o[nt][half * 2 + 1] *= corr;
            }
        }

        // ---- O += P V (V hi + lo) ----
        #pragma unroll
        for (int kc = 0; kc < 4; kc++) {
            uint32_t a[4];
            a[0] = pack_bf2(sv[2 * kc][0],     sv[2 * kc][1]);
            a[1] = pack_bf2(sv[2 * kc][2],     sv[2 * kc][3]);
            a[2] = pack_bf2(sv[2 * kc + 1][0], sv[2 * kc + 1][1]);
            a[3] = pack_bf2(sv[2 * kc + 1][2], sv[2 * kc + 1][3]);
            uint32_t vh[16], vl[16];
            #pragma unroll
            for (int np = 0; np < 4; np++) {
                uint32_t ro = swz((uint32_t)(kc * 16 + (lane & 7) + ((lane >> 3) & 1) * 8) * 128u
                                  + (uint32_t)(np * 16 + ((lane >> 4) & 1) * 8) * 2u);
                ldm4t(&vh[np * 4], VB + ro);
                ldm4t(&vl[np * 4], VB + 8192u + ro);
            }
            #pragma unroll
            for (int nt = 0; nt < 8; nt++) {
                mma_bf16(o[nt], a, &vh[nt * 2]);
                mma_bf16(o[nt], a, &vl[nt * 2]);
            }
        }
        __syncthreads();
    }

    // ---- epilogue ----
    float inv0 = 1.0f / lrow[0], inv1 = 1.0f / lrow[1];
    int tok0 = b * SEQ + s0 + m_warp + (lane >> 2);
    int colb = h * HD + (lane & 3) * 2;
    #pragma unroll
    for (int nt = 0; nt < 8; nt++) {
        int c = colb + nt * 8;
        __nv_bfloat16* p0 = outbf + (size_t)tok0 * 2 * HDIM + c;
        store_hilo2(p0, p0 + HDIM, make_float2(o[nt][0] * inv0, o[nt][1] * inv0));
        __nv_bfloat16* p1 = outbf + (size_t)(tok0 + 8) * 2 * HDIM + c;
        store_hilo2(p1, p1 + HDIM, make_float2(o[nt][2] * inv1, o[nt][3] * inv1));
    }
}

// ---------------- routing ----------------
__global__ void router_kernel(const float* __restrict__ hf, const float* __restrict__ rw) {
    int t = blockIdx.x, tid = threadIdx.x;
    int w = tid >> 5, lane = tid & 31;
    __shared__ float logits[NE];
    float s = 0.0f;
    for (int i = lane; i < HDIM; i += 32)
        s += hf[(size_t)t * HDIM + i] * __ldg(rw + (size_t)i * NE + w);
    #pragma unroll
    for (int o = 16; o; o >>= 1) s += __shfl_xor_sync(0xffffffffu, s, o);
    if (lane == 0) logits[w] = s;
    __syncthreads();
    if (tid == 0) {
        int e0 = 0; float b0 = logits[0];
        #pragma unroll
        for (int e = 1; e < NE; e++) if (logits[e] > b0) { b0 = logits[e]; e0 = e; }
        int e1 = -1; float b1 = -3.0e38f;
        #pragma unroll
        for (int e = 0; e < NE; e++)
            if (e != e0 && logits[e] > b1) { b1 = logits[e]; e1 = e; }
        float w0 = 1.0f / (1.0f + expf(b1 - b0));
        g_tok_e[t * 2 + 0] = e0;
        g_tok_e[t * 2 + 1] = e1;
        g_tok_w[t * 2 + 0] = w0;
        g_tok_w[t * 2 + 1] = 1.0f - w0;
        atomicAdd(&g_cnt[e0], 1);
        atomicAdd(&g_cnt[e1], 1);
    }
}

__global__ void scan_kernel() {
    if (threadIdx.x == 0) {
        int acc = 0;
        for (int e = 0; e < NE; e++) { g_off[e] = acc; acc += g_cnt[e]; g_cur[e] = 0; }
    }
}

__global__ void assign_gather_kernel(const float* __restrict__ hf) {
    int t = blockIdx.x, tid = threadIdx.x;
    __shared__ int sl[2];
    if (tid < 2) {
        int e = g_tok_e[t * 2 + tid];
        int s = g_off[e] + atomicAdd(&g_cur[e], 1);
        sl[tid] = s;
        g_tok_slot[t * 2 + tid] = s;
    }
    __syncthreads();
    float4 v = ((const float4*)(hf + (size_t)t * HDIM))[tid];
    #pragma unroll
    for (int k = 0; k < 2; k++) {
        __nv_bfloat16* base = g_xgbf + (size_t)sl[k] * 2 * HDIM;
        store_hilo4(base + tid * 4, base + HDIM + tid * 4, v);
    }
}

__global__ void silu_kernel() {
    size_t idx = (size_t)blockIdx.x * 256 + threadIdx.x;
    int row = (int)(idx >> 9);
    int jj = (int)(idx & 511) << 2;
    const float* g = g_gu + (size_t)row * (2 * INTER) + jj;
    float4 gv = *(const float4*)g;
    float4 uv = *(const float4*)(g + INTER);
    float4 r;
    r.x = gv.x / (1.0f + __expf(-gv.x)) * uv.x;
    r.y = gv.y / (1.0f + __expf(-gv.y)) * uv.y;
    r.z = gv.z / (1.0f + __expf(-gv.z)) * uv.z;
    r.w = gv.w / (1.0f + __expf(-gv.w)) * uv.w;
    __nv_bfloat16* base = g_actbf + (size_t)row * 2 * INTER;
    store_hilo4(base + jj, base + INTER + jj, r);
}

__global__ void combine_kernel(float* __restrict__ out) {
    int t = blockIdx.x, tid = threadIdx.x;
    int s0 = g_tok_slot[t * 2 + 0], s1 = g_tok_slot[t * 2 + 1];
    float w0 = g_tok_w[t * 2 + 0], w1 = g_tok_w[t * 2 + 1];
    float4 x = ((float4*)(out + (size_t)t * HDIM))[tid];
    float4 a = ((const float4*)(g_dn + (size_t)s0 * HDIM))[tid];
    float4 b = ((const float4*)(g_dn + (size_t)s1 * HDIM))[tid];
    x.x += w0 * a.x + w1 * b.x;
    x.y += w0 * a.y + w1 * b.y;
    x.z += w0 * a.z + w1 * b.z;
    x.w += w0 * a.w + w1 * b.w;
    ((float4*)(out + (size_t)t * HDIM))[tid] = x;
}

// ---------------- launch ----------------
extern "C" void kernel_launch(void* const* d_in, const int* in_sizes, int n_in,
                              void* d_out, int out_size) {
    const float* hidden = (const float*)d_in[0];
    const float* mask   = (const float*)d_in[1];
    const float* ln1    = (const float*)d_in[2];
    const float* ln2    = (const float*)d_in[3];
    const float* qkv_w  = (const float*)d_in[4];
    const float* o_w    = (const float*)d_in[5];
    const float* rt_w   = (const float*)d_in[6];
    const float* gup    = (const float*)d_in[7];
    const float* dwn    = (const float*)d_in[8];
    float* out = (float*)d_out;

    float *hfb, *gu, *dn;
    __nv_bfloat16 *qkvbf, *hnbf, *attnbf, *xgbf, *actbf, *qkvwt, *owt, *gupt, *dwnt;
    cudaGetSymbolAddress((void**)&hfb,   g_hf);
    cudaGetSymbolAddress((void**)&gu,    g_gu);
    cudaGetSymbolAddress((void**)&dn,    g_dn);
    cudaGetSymbolAddress((void**)&qkvbf, g_qkvbf);
    cudaGetSymbolAddress((void**)&hnbf,  g_hnbf);
    cudaGetSymbolAddress((void**)&attnbf, g_attnbf);
    cudaGetSymbolAddress((void**)&xgbf,  g_xgbf);
    cudaGetSymbolAddress((void**)&actbf, g_actbf);
    cudaGetSymbolAddress((void**)&qkvwt, g_qkvwt);
    cudaGetSymbolAddress((void**)&owt,   g_owt);
    cudaGetSymbolAddress((void**)&gupt,  g_gupt);
    cudaGetSymbolAddress((void**)&dwnt,  g_dwnt);

    cudaFuncSetAttribute(attn_mma_kernel, cudaFuncAttributeMaxDynamicSharedMemorySize, ATTN2_SMEM);
    cudaFuncSetAttribute(gemm_bf3, cudaFuncAttributeMaxDynamicSharedMemorySize, GSMEM);
    cudaFuncSetAttribute(gemm_moe3, cudaFuncAttributeMaxDynamicSharedMemorySize, GSMEM);

    zero_kernel<<<1, 32>>>();

    // weight transpose + hi/lo split
    wconv_kernel<<<dim3(TQKV / 32, HDIM / 64, 1), 256>>>(qkv_w, qkvwt, HDIM, TQKV);
    wconv_kernel<<<dim3(HDIM / 32, HDIM / 64, 1), 256>>>(o_w, owt, HDIM, HDIM);
    wconv_kernel<<<dim3(2 * INTER / 32, HDIM / 64, NE), 256>>>(gup, gupt, HDIM, 2 * INTER);
    wconv_kernel<<<dim3(HDIM / 32, INTER / 64, NE), 256>>>(dwn, dwnt, INTER, HDIM);

    // attention block
    rmsnorm_kernel<<<NTOK, 256>>>(hidden, ln1, nullptr, hnbf);
    gemm_bf3<<<dim3(TQKV / 128, NTOK / 128), 256, GSMEM>>>(
        hnbf, 2 * HDIM, qkvwt, 2 * HDIM, nullptr, 0, HDIM, nullptr,
        qkvbf, 2 * TQKV, TQKV);
    attn_mma_kernel<<<dim3(SEQ / 128, NBATCH * NH), 256, ATTN2_SMEM>>>(qkvbf, mask, attnbf);
    gemm_bf3<<<dim3(HDIM / 128, NTOK / 128), 256, GSMEM>>>(
        attnbf, 2 * HDIM, owt, 2 * HDIM, out, HDIM, HDIM, hidden,
        nullptr, 0, 0);

    // moe block
    rmsnorm_kernel<<<NTOK, 256>>>(out, ln2, hfb, nullptr);
    router_kernel<<<NTOK, 256>>>(hfb, rt_w);
    scan_kernel<<<1, 32>>>();
    assign_gather_kernel<<<NTOK, 256>>>(hfb);

    gemm_moe3<<<dim3(2 * INTER / 128, NTOK / 128, NE), 256, GSMEM>>>(
        xgbf, 2 * HDIM, gupt, 2 * HDIM, (long long)(2 * INTER) * 2 * HDIM,
        gu, 2 * INTER, HDIM);
    silu_kernel<<<(SLOTS * (INTER / 4)) / 256, 256>>>();
    gemm_moe3<<<dim3(HDIM / 128, NTOK / 128, NE), 256, GSMEM>>>(
        actbf, 2 * INTER, dwnt, 2 * INTER, (long long)HDIM * 2 * INTER,
        dn, HDIM, INTER);

    combine_kernel<<<NTOK, 256>>>(out);
}